// round 15
// baseline (speedup 1.0000x reference)
#include <cuda_runtime.h>
#include <cuda_bf16.h>

#define BATCH 4
#define NP    8192
#define NQ    2048
#define CF    64
#define CT    64
#define KS    32
#define R2    0.04f
#define OUTC  (3 + CF)        // 67 channels in grouped_features
#define QPB   32              // queries per ball-query block

__device__ uint2 g_idx16_v[BATCH * NQ * KS / 4];   // ushort idx, 4 per uint2

// Ball query: whole batch cloud in 96KB dynamic smem (SoA). 256 blocks,
// 2 blocks/SM (launch_bounds(1024,2) caps regs at 32), one query per warp.
__global__ __launch_bounds__(1024, 2) void qg_ballquery_kernel(
    const float* __restrict__ coords,
    const float* __restrict__ queries,
    float* __restrict__ out)
{
    extern __shared__ float sxyz[];                  // sx[NP] | sy[NP] | sz[NP]
    float* sx = sxyz;
    __shared__ int slots_s[32][KS];

    int tid  = threadIdx.x;
    int lane = tid & 31;
    int w    = tid >> 5;
    int b    = blockIdx.x >> 6;                      // 64 blocks per batch
    int blk  = blockIdx.x & 63;

    const float* cb = coords + (size_t)b * NP * 3;
    #pragma unroll
    for (int j = 0; j < (NP * 3) / 1024; ++j) {
        int i = tid + j * 1024;
        float v = cb[i];
        int p = i / 3, d = i - 3 * p;
        sxyz[d * NP + p] = v;
    }
    __syncthreads();

    float* sy = sxyz + NP;
    float* sz = sxyz + 2 * NP;
    int* slots = slots_s[w];
    unsigned lt = (1u << lane) - 1u;
    const size_t stride = (size_t)NQ * KS;

    int q = blk * QPB + w;
    int g = b * NQ + q;
    const float* qp = queries + (size_t)g * 3;
    float qx = qp[0], qy = qp[1], qz = qp[2];

    int count = 0;
    for (int base = 0; base < NP; base += 64) {
        int i0 = base + lane, i1 = base + 32 + lane;
        float x0 = sx[i0], y0 = sy[i0], z0 = sz[i0];
        float x1 = sx[i1], y1 = sy[i1], z1 = sz[i1];
        // Match XLA rounding exactly: no FMA contraction.
        float dx0 = __fadd_rn(qx, -x0), dy0 = __fadd_rn(qy, -y0), dz0 = __fadd_rn(qz, -z0);
        float d20 = __fadd_rn(__fadd_rn(__fmul_rn(dx0, dx0), __fmul_rn(dy0, dy0)),
                              __fmul_rn(dz0, dz0));
        float dx1 = __fadd_rn(qx, -x1), dy1 = __fadd_rn(qy, -y1), dz1 = __fadd_rn(qz, -z1);
        float d21 = __fadd_rn(__fadd_rn(__fmul_rn(dx1, dx1), __fmul_rn(dy1, dy1)),
                              __fmul_rn(dz1, dz1));
        bool in0 = d20 < R2;
        bool in1 = d21 < R2;
        unsigned m0 = __ballot_sync(0xffffffffu, in0);
        unsigned m1 = __ballot_sync(0xffffffffu, in1);
        if (in0) {
            int s = count + __popc(m0 & lt);
            if (s < KS) slots[s] = i0;
        }
        int c1 = count + __popc(m0);
        if (in1) {
            int s = c1 + __popc(m1 & lt);
            if (s < KS) slots[s] = i1;
        }
        count = c1 + __popc(m1);
        if (count >= KS) break;
    }
    __syncwarp();

    int cnt   = count < KS ? count : KS;
    int first = (count > 0) ? slots[0] : 0;
    int my    = (lane < cnt) ? slots[lane] : first;
    ((unsigned short*)g_idx16_v)[(size_t)g * KS + lane] = (unsigned short)my;

    size_t ob0 = (size_t)b * OUTC * stride + (size_t)q * KS + lane;
    out[ob0]              = sx[my] - qx;
    out[ob0 + stride]     = sy[my] - qy;
    out[ob0 + 2 * stride] = sz[my] - qz;
}

// Gather: block per (batch, channel-pair, query-chunk) = 512 blocks, 64KB smem,
// 512 threads (3 blocks/SM = 1536 thr, 2x warps vs 256-thr version).
// ushort idx (uint2 = 4 indices), 4 prefetched streams.
__global__ __launch_bounds__(512) void qg_gather_kernel(
    const float* __restrict__ feats,
    const float* __restrict__ temb,
    float* __restrict__ out)
{
    extern __shared__ float2 rows[];    // [NP] interleaved channel pair (64KB)

    int tid   = threadIdx.x;
    int bc    = blockIdx.x;             // 0..511
    int chunk = bc & 1;
    int pair  = (bc >> 1) & 63;
    int b     = bc >> 7;
    int cc    = pair * 2;               // 0..126
    int which = cc >> 6;
    int ch    = cc & 63;

    const float* s0 = (which ? temb : feats) + ((size_t)b * 64 + ch) * NP;
    for (int p = tid; p < NP; p += 512)
        rows[p] = make_float2(s0[p], s0[NP + p]);
    __syncthreads();

    const size_t stride = (size_t)NQ * KS;
    size_t ob0;
    if (which == 0)
        ob0 = (size_t)b * OUTC * stride + (size_t)(3 + ch) * stride;
    else
        ob0 = (size_t)BATCH * OUTC * stride + (size_t)b * CT * stride + (size_t)ch * stride;
    size_t ob1 = ob0 + stride;

    // Per batch: 16384 uint2 groups; this chunk: 8192 = 4 streams x 2048.
    const uint2* idxp = g_idx16_v + (size_t)b * (NQ * KS / 4) + chunk * 8192;

    uint2 cur0 = idxp[0 * 2048 + tid];
    uint2 cur1 = idxp[1 * 2048 + tid];
    uint2 cur2 = idxp[2 * 2048 + tid];
    uint2 cur3 = idxp[3 * 2048 + tid];

    #pragma unroll
    for (int it = 0; it < 4; ++it) {
        uint2 n0, n1, n2, n3;
        if (it < 3) {
            int o = (it + 1) * 512 + tid;
            n0 = idxp[0 * 2048 + o];
            n1 = idxp[1 * 2048 + o];
            n2 = idxp[2 * 2048 + o];
            n3 = idxp[3 * 2048 + o];
        }
        #pragma unroll
        for (int s = 0; s < 4; ++s) {
            uint2 u = (s == 0) ? cur0 : (s == 1) ? cur1 : (s == 2) ? cur2 : cur3;
            int ge = chunk * 8192 + s * 2048 + it * 512 + tid;   // group id in batch
            float2 f0 = rows[u.x & 0xffff];
            float2 f1 = rows[u.x >> 16];
            float2 f2 = rows[u.y & 0xffff];
            float2 f3 = rows[u.y >> 16];
            size_t pe = (size_t)ge * 4;
            *(float4*)(out + ob0 + pe) = make_float4(f0.x, f1.x, f2.x, f3.x);
            *(float4*)(out + ob1 + pe) = make_float4(f0.y, f1.y, f2.y, f3.y);
        }
        cur0 = n0; cur1 = n1; cur2 = n2; cur3 = n3;
    }
}

extern "C" void kernel_launch(void* const* d_in, const int* in_sizes, int n_in,
                              void* d_out, int out_size) {
    const float* coords  = (const float*)d_in[0];  // [B,Np,3]
    const float* feats   = (const float*)d_in[1];  // [B,C,Np]
    const float* temb    = (const float*)d_in[2];  // [B,Ct,Np]
    const float* queries = (const float*)d_in[3];  // [B,Nq,3]
    float* out = (float*)d_out;

    const int bq_smem = 3 * NP * (int)sizeof(float);    // 96KB
    const int gt_smem = NP * (int)sizeof(float2);       // 64KB
    cudaFuncSetAttribute(qg_ballquery_kernel,
                         cudaFuncAttributeMaxDynamicSharedMemorySize, bq_smem);
    cudaFuncSetAttribute(qg_gather_kernel,
                         cudaFuncAttributeMaxDynamicSharedMemorySize, gt_smem);

    qg_ballquery_kernel<<<BATCH * 64, 1024, bq_smem>>>(coords, queries, out);
    qg_gather_kernel<<<512, 512, gt_smem>>>(feats, temb, out);
}

// round 16
// speedup vs baseline: 1.0874x; 1.0874x over previous
#include <cuda_runtime.h>
#include <cuda_bf16.h>

#define BATCH 4
#define NP    8192
#define NQ    2048
#define CF    64
#define CT    64
#define KS    32
#define R2    0.04f
#define OUTC  (3 + CF)        // 67 channels in grouped_features
#define QPB   64              // queries per ball-query block

__device__ uint2 g_idx16_v[BATCH * NQ * KS / 4];   // ushort idx, 4 per uint2

// Ball query: whole batch cloud in 96KB dynamic smem (SoA). 128 blocks, 1024
// threads. Each warp handles TWO queries INTERLEAVED, sharing the smem point
// loads between them (halves LDS per query; iterations = max of the two scans).
__global__ __launch_bounds__(1024) void qg_ballquery_kernel(
    const float* __restrict__ coords,
    const float* __restrict__ queries,
    float* __restrict__ out)
{
    extern __shared__ float sxyz[];                  // sx[NP] | sy[NP] | sz[NP]
    float* sx = sxyz;
    __shared__ int slots_s[32][2][KS];               // 8KB

    int tid  = threadIdx.x;
    int lane = tid & 31;
    int w    = tid >> 5;
    int b    = blockIdx.x >> 5;                      // 32 blocks per batch
    int blk  = blockIdx.x & 31;

    const float* cb = coords + (size_t)b * NP * 3;
    #pragma unroll
    for (int j = 0; j < (NP * 3) / 1024; ++j) {
        int i = tid + j * 1024;
        float v = cb[i];
        int p = i / 3, d = i - 3 * p;
        sxyz[d * NP + p] = v;
    }
    __syncthreads();

    float* sy = sxyz + NP;
    float* sz = sxyz + 2 * NP;
    unsigned lt = (1u << lane) - 1u;
    const size_t stride = (size_t)NQ * KS;

    int qA = blk * QPB + w;
    int qB = qA + 32;
    int gA = b * NQ + qA;
    int gB = b * NQ + qB;
    const float* qpA = queries + (size_t)gA * 3;
    const float* qpB = queries + (size_t)gB * 3;
    float ax = qpA[0], ay = qpA[1], az = qpA[2];
    float bx = qpB[0], by = qpB[1], bz = qpB[2];

    int cntA = 0, cntB = 0;
    for (int base = 0; base < NP; base += 64) {
        int i0 = base + lane, i1 = base + 32 + lane;
        // Shared point loads (serve both queries).
        float x0 = sx[i0], y0 = sy[i0], z0 = sz[i0];
        float x1 = sx[i1], y1 = sy[i1], z1 = sz[i1];
        // Match XLA rounding exactly: no FMA contraction.
        float dxa0 = __fadd_rn(ax, -x0), dya0 = __fadd_rn(ay, -y0), dza0 = __fadd_rn(az, -z0);
        float dA0 = __fadd_rn(__fadd_rn(__fmul_rn(dxa0, dxa0), __fmul_rn(dya0, dya0)),
                              __fmul_rn(dza0, dza0));
        float dxa1 = __fadd_rn(ax, -x1), dya1 = __fadd_rn(ay, -y1), dza1 = __fadd_rn(az, -z1);
        float dA1 = __fadd_rn(__fadd_rn(__fmul_rn(dxa1, dxa1), __fmul_rn(dya1, dya1)),
                              __fmul_rn(dza1, dza1));
        float dxb0 = __fadd_rn(bx, -x0), dyb0 = __fadd_rn(by, -y0), dzb0 = __fadd_rn(bz, -z0);
        float dB0 = __fadd_rn(__fadd_rn(__fmul_rn(dxb0, dxb0), __fmul_rn(dyb0, dyb0)),
                              __fmul_rn(dzb0, dzb0));
        float dxb1 = __fadd_rn(bx, -x1), dyb1 = __fadd_rn(by, -y1), dzb1 = __fadd_rn(bz, -z1);
        float dB1 = __fadd_rn(__fadd_rn(__fmul_rn(dxb1, dxb1), __fmul_rn(dyb1, dyb1)),
                              __fmul_rn(dzb1, dzb1));
        bool inA0 = dA0 < R2, inA1 = dA1 < R2;
        bool inB0 = dB0 < R2, inB1 = dB1 < R2;
        unsigned mA0 = __ballot_sync(0xffffffffu, inA0);
        unsigned mA1 = __ballot_sync(0xffffffffu, inA1);
        unsigned mB0 = __ballot_sync(0xffffffffu, inB0);
        unsigned mB1 = __ballot_sync(0xffffffffu, inB1);
        if (cntA < KS) {
            if (inA0) {
                int s = cntA + __popc(mA0 & lt);
                if (s < KS) slots_s[w][0][s] = i0;
            }
            int c1 = cntA + __popc(mA0);
            if (inA1) {
                int s = c1 + __popc(mA1 & lt);
                if (s < KS) slots_s[w][0][s] = i1;
            }
        }
        cntA += __popc(mA0) + __popc(mA1);
        if (cntB < KS) {
            if (inB0) {
                int s = cntB + __popc(mB0 & lt);
                if (s < KS) slots_s[w][1][s] = i0;
            }
            int c1 = cntB + __popc(mB0);
            if (inB1) {
                int s = c1 + __popc(mB1 & lt);
                if (s < KS) slots_s[w][1][s] = i1;
            }
        }
        cntB += __popc(mB0) + __popc(mB1);
        if (cntA >= KS && cntB >= KS) break;
    }
    __syncwarp();

    // NOTE: counts may have appended past-K within a final iteration, but slot
    // writes were guarded by pre-iteration count<KS and per-append s<KS, and
    // append order is index order, so slots[0..KS) hold the first-K exactly.
    {
        int firstA = (cntA > 0) ? slots_s[w][0][0] : 0;
        int myA    = (lane < (cntA < KS ? cntA : KS)) ? slots_s[w][0][lane] : firstA;
        ((unsigned short*)g_idx16_v)[(size_t)gA * KS + lane] = (unsigned short)myA;
        size_t ob = (size_t)b * OUTC * stride + (size_t)qA * KS + lane;
        out[ob]              = sx[myA] - ax;
        out[ob + stride]     = sy[myA] - ay;
        out[ob + 2 * stride] = sz[myA] - az;
    }
    {
        int firstB = (cntB > 0) ? slots_s[w][1][0] : 0;
        int myB    = (lane < (cntB < KS ? cntB : KS)) ? slots_s[w][1][lane] : firstB;
        ((unsigned short*)g_idx16_v)[(size_t)gB * KS + lane] = (unsigned short)myB;
        size_t ob = (size_t)b * OUTC * stride + (size_t)qB * KS + lane;
        out[ob]              = sx[myB] - bx;
        out[ob + stride]     = sy[myB] - by;
        out[ob + 2 * stride] = sz[myB] - bz;
    }
}

// Gather (exact R13 best config): block per (batch, channel-pair, query-chunk)
// = 512 blocks, 256 threads, 64KB smem, ushort idx, 4 prefetched streams.
__global__ __launch_bounds__(256) void qg_gather_kernel(
    const float* __restrict__ feats,
    const float* __restrict__ temb,
    float* __restrict__ out)
{
    extern __shared__ float2 rows[];    // [NP] interleaved channel pair (64KB)

    int tid   = threadIdx.x;
    int bc    = blockIdx.x;             // 0..511
    int chunk = bc & 1;
    int pair  = (bc >> 1) & 63;
    int b     = bc >> 7;
    int cc    = pair * 2;               // 0..126
    int which = cc >> 6;
    int ch    = cc & 63;

    const float* s0 = (which ? temb : feats) + ((size_t)b * 64 + ch) * NP;
    for (int p = tid; p < NP; p += 256)
        rows[p] = make_float2(s0[p], s0[NP + p]);
    __syncthreads();

    const size_t stride = (size_t)NQ * KS;
    size_t ob0;
    if (which == 0)
        ob0 = (size_t)b * OUTC * stride + (size_t)(3 + ch) * stride;
    else
        ob0 = (size_t)BATCH * OUTC * stride + (size_t)b * CT * stride + (size_t)ch * stride;
    size_t ob1 = ob0 + stride;

    const uint2* idxp = g_idx16_v + (size_t)b * (NQ * KS / 4) + chunk * 8192;

    uint2 cur0 = idxp[0 * 2048 + tid];
    uint2 cur1 = idxp[1 * 2048 + tid];
    uint2 cur2 = idxp[2 * 2048 + tid];
    uint2 cur3 = idxp[3 * 2048 + tid];

    #pragma unroll
    for (int it = 0; it < 8; ++it) {
        uint2 n0, n1, n2, n3;
        if (it < 7) {
            int o = (it + 1) * 256 + tid;
            n0 = idxp[0 * 2048 + o];
            n1 = idxp[1 * 2048 + o];
            n2 = idxp[2 * 2048 + o];
            n3 = idxp[3 * 2048 + o];
        }
        #pragma unroll
        for (int s = 0; s < 4; ++s) {
            uint2 u = (s == 0) ? cur0 : (s == 1) ? cur1 : (s == 2) ? cur2 : cur3;
            int ge = chunk * 8192 + s * 2048 + it * 256 + tid;   // group id in batch
            float2 f0 = rows[u.x & 0xffff];
            float2 f1 = rows[u.x >> 16];
            float2 f2 = rows[u.y & 0xffff];
            float2 f3 = rows[u.y >> 16];
            size_t pe = (size_t)ge * 4;
            *(float4*)(out + ob0 + pe) = make_float4(f0.x, f1.x, f2.x, f3.x);
            *(float4*)(out + ob1 + pe) = make_float4(f0.y, f1.y, f2.y, f3.y);
        }
        cur0 = n0; cur1 = n1; cur2 = n2; cur3 = n3;
    }
}

extern "C" void kernel_launch(void* const* d_in, const int* in_sizes, int n_in,
                              void* d_out, int out_size) {
    const float* coords  = (const float*)d_in[0];  // [B,Np,3]
    const float* feats   = (const float*)d_in[1];  // [B,C,Np]
    const float* temb    = (const float*)d_in[2];  // [B,Ct,Np]
    const float* queries = (const float*)d_in[3];  // [B,Nq,3]
    float* out = (float*)d_out;

    const int bq_smem = 3 * NP * (int)sizeof(float);    // 96KB
    const int gt_smem = NP * (int)sizeof(float2);       // 64KB
    cudaFuncSetAttribute(qg_ballquery_kernel,
                         cudaFuncAttributeMaxDynamicSharedMemorySize, bq_smem);
    cudaFuncSetAttribute(qg_gather_kernel,
                         cudaFuncAttributeMaxDynamicSharedMemorySize, gt_smem);

    qg_ballquery_kernel<<<BATCH * 32, 1024, bq_smem>>>(coords, queries, out);
    qg_gather_kernel<<<512, 256, gt_smem>>>(feats, temb, out);
}